// round 12
// baseline (speedup 1.0000x reference)
#include <cuda_runtime.h>

// Exact integer reformulation of the PUMA crossbar MVM conv (validated R1-R11):
//   out = RNE_clip( conv_int(xi16, dw) / 4096 ) / 4096
//   xi16 = sext16(rint(x*4096)),  dw = clamp(rint(w*4096), +/-65535)
//
// R12: 4 ow-columns per thread -> each 16B w-load feeds 16 IMADs (was 8),
// cutting mainloop SMEM wavefronts from ~42 to ~24 per warp-ci. Balance
// shifts from SMEM/IMAD co-bound to IMAD-bound. Lanes: p(4 col-quads) x
// cog(2 of 4 Cout) x ohsub(2) x half(2); warps = 4 ci-quarters -> 8-way ci
// split (quarter x half). Half-pairs combined via shfl_xor(16), quarters via
// SMEM reduction. Grid 512 x 128 threads, occ 4, single wave.

namespace {
constexpr int CIN = 64, H = 16, W = 16, COUT = 128;
constexpr int L = CIN * 9;        // 576
constexpr int CO_CHUNK = 8;
constexpr int THREADS = 128;
}

__device__ __forceinline__ float rne_fix(int S) {
    int base = S >> 12;                 // floor(S/4096)
    int rem  = S - (base << 12);        // 0..4095
    if (rem > 2048)       base += 1;
    else if (rem == 2048) base += (base & 1);   // ties to even
    base = max(-32768, min(32767, base));
    return (float)base * (1.0f / 4096.0f);
}

__global__ __launch_bounds__(THREADS, 4)
void conv_mvm_kernel(const float* __restrict__ x,
                     const float* __restrict__ w,
                     float* __restrict__ out)
{
    __shared__ int sw[L * CO_CHUNK];   // 18432 B : [l][co_local(8)]
    __shared__ int sx[CIN * 4 * 16];   // 16384 B : [ci][r 0..3][col 0..15] sext16
    __shared__ int red[3][16][16];     //  3072 B : quarters 1..3 partials

    const int bid     = blockIdx.x;       // 512 = 16 chunks x 8 ohp x 4 b
    const int coChunk = bid & 15;
    const int ohp     = (bid >> 4) & 7;
    const int b       = bid >> 7;

    const int tid     = threadIdx.x;
    const int p       = tid & 3;          // col quad -> cols 4p .. 4p+3
    const int cog     = (tid >> 2) & 1;   // group of 4 Cout
    const int ohsub   = (tid >> 3) & 1;   // output row within pair
    const int half    = (tid >> 4) & 1;   // ci half within quarter
    const int quarter = tid >> 5;         // warp id = ci quarter

    // ---- stage weights: co-major lane mapping, conflict-free STS (R11) ----
    {
        const float* wsrc = w + coChunk * CO_CHUNK * L;
        #pragma unroll
        for (int it = 0; it < (CO_CHUNK * L) / THREADS; ++it) {   // 36 iters
            int idx = it * THREADS + tid;
            int co  = idx & 7;
            int l   = idx >> 3;
            int q = __float2int_rn(wsrc[co * L + l] * 4096.0f);
            q = max(-65535, min(65535, q));
            sw[idx] = q;                  // == sw[l * CO_CHUNK + co]
        }
    }

    // ---- stage inputs: float4 LDG + sext16, int4 STS (R10/R11) ----
    #pragma unroll
    for (int it = 0; it < (CIN * 4 * 16 / 4) / THREADS; ++it) {   // 8 iters
        int vidx = it * THREADS + tid;
        int colv = vidx & 3;
        int r    = (vidx >> 2) & 3;
        int ci   = vidx >> 4;
        int gr   = ohp * 2 - 1 + r;
        int4 v = make_int4(0, 0, 0, 0);
        if ((unsigned)gr < (unsigned)H) {
            float4 xv = *(const float4*)&x[((b * CIN + ci) * H + gr) * W + colv * 4];
            v.x = (__float2int_rn(xv.x * 4096.0f) << 16) >> 16;
            v.y = (__float2int_rn(xv.y * 4096.0f) << 16) >> 16;
            v.z = (__float2int_rn(xv.z * 4096.0f) << 16) >> 16;
            v.w = (__float2int_rn(xv.w * 4096.0f) << 16) >> 16;
        }
        *((int4*)sx + vidx) = v;
    }
    __syncthreads();

    // ---- mainloop: 8 ci x (3 LDS.128 x + 9 LDS.128 w + 144 IMAD) ----
    // A[c][kj][m] += x[row][4p+c] * w[kj][m]
    int A[4][3][4] = {};
    const int ciBase = quarter * 16 + half * 8;
    #pragma unroll 2
    for (int i = 0; i < 8; ++i) {
        const int ci = ciBase + i;
        const int* xp = &sx[(ci * 4 + ohsub) * 16 + p * 4];
        const int* wp = &sw[ci * 9 * CO_CHUNK + cog * 4];
        #pragma unroll
        for (int ki = 0; ki < 3; ++ki) {
            int4 xv = *(const int4*)&xp[ki * 16];   // cols 4p..4p+3, row ohsub+ki
            #pragma unroll
            for (int kj = 0; kj < 3; ++kj) {
                int4 wv = *(const int4*)&wp[(ki * 3 + kj) * CO_CHUNK];
                A[0][kj][0] += xv.x * wv.x;  A[0][kj][1] += xv.x * wv.y;
                A[0][kj][2] += xv.x * wv.z;  A[0][kj][3] += xv.x * wv.w;
                A[1][kj][0] += xv.y * wv.x;  A[1][kj][1] += xv.y * wv.y;
                A[1][kj][2] += xv.y * wv.z;  A[1][kj][3] += xv.y * wv.w;
                A[2][kj][0] += xv.z * wv.x;  A[2][kj][1] += xv.z * wv.y;
                A[2][kj][2] += xv.z * wv.z;  A[2][kj][3] += xv.z * wv.w;
                A[3][kj][0] += xv.w * wv.x;  A[3][kj][1] += xv.w * wv.y;
                A[3][kj][2] += xv.w * wv.z;  A[3][kj][3] += xv.w * wv.w;
            }
        }
    }

    // ---- sliding-window combine: out[4p+j] = sum over (c,kj), c-kj+1 = j ----
    // Edge terms come from neighbor quads via shuffle (width 4 over p);
    // cols -1 and 16 are pad == 0, so p-edge lanes zero them exactly.
    const unsigned m32 = 0xFFFFFFFFu;
    int s[4][4];
    #pragma unroll
    for (int m = 0; m < 4; ++m) {
        int up = __shfl_up_sync(m32, A[3][0][m], 1, 4);    // neighbor c=3,kj=0 -> j=0
        int dn = __shfl_down_sync(m32, A[0][2][m], 1, 4);  // neighbor c=0,kj=2 -> j=3
        if (p == 0) up = 0;
        if (p == 3) dn = 0;
        s[0][m] = up        + A[0][1][m] + A[1][2][m];
        s[1][m] = A[0][0][m] + A[1][1][m] + A[2][2][m];
        s[2][m] = A[1][0][m] + A[2][1][m] + A[3][2][m];
        s[3][m] = A[2][0][m] + A[3][1][m] + dn;
    }

    // ---- combine ci-halves: lanes differing in bit4 hold the same output ----
    #pragma unroll
    for (int j = 0; j < 4; ++j)
        #pragma unroll
        for (int m = 0; m < 4; ++m)
            s[j][m] += __shfl_xor_sync(m32, s[j][m], 16);

    // ---- reduce ci-quarters via SMEM (half-0 lanes carry the sums) ----
    const int lane16 = tid & 15;                 // (p, cog, ohsub)
    if (quarter != 0 && half == 0) {
        int* dst = &red[quarter - 1][lane16][0];
        #pragma unroll
        for (int j = 0; j < 4; ++j)
            #pragma unroll
            for (int m = 0; m < 4; ++m)
                dst[j * 4 + m] = s[j][m];
    }
    __syncthreads();
    if (quarter != 0 || half != 0) return;

    #pragma unroll
    for (int q = 0; q < 3; ++q) {
        const int* src = &red[q][lane16][0];
        #pragma unroll
        for (int j = 0; j < 4; ++j)
            #pragma unroll
            for (int m = 0; m < 4; ++m)
                s[j][m] += src[j * 4 + m];
    }

    // ---- epilogue: RNE to 1/4096 grid, clip int16, STG.128 per Cout ----
    const int oh    = ohp * 2 + ohsub;
    const int coOut = coChunk * CO_CHUNK + cog * 4;
    const int ow0   = p * 4;
    #pragma unroll
    for (int m = 0; m < 4; ++m) {
        float4 o;
        o.x = rne_fix(s[0][m]);
        o.y = rne_fix(s[1][m]);
        o.z = rne_fix(s[2][m]);
        o.w = rne_fix(s[3][m]);
        *(float4*)&out[((b * COUT + coOut + m) * H + oh) * W + ow0] = o;
    }
}

extern "C" void kernel_launch(void* const* d_in, const int* in_sizes, int n_in,
                              void* d_out, int out_size) {
    const float* x = (const float*)d_in[0];
    const float* w = (const float*)d_in[1];
    // defensive: identify tensors by element count (x: 65536, w: 73728)
    if (n_in >= 2 && in_sizes[0] == 73728 && in_sizes[1] == 65536) {
        x = (const float*)d_in[1];
        w = (const float*)d_in[0];
    }
    conv_mvm_kernel<<<512, THREADS>>>(x, w, (float*)d_out);
}